// round 14
// baseline (speedup 1.0000x reference)
#include <cuda_runtime.h>
#include <cuda_fp16.h>
#include <math.h>

// x = (4, 64, 128, 128) fp32, K=7 -> out (4, 49, 16384) fp32
#define BATCH   4
#define CHN     64
#define HT      128
#define WD      128
#define HW      (HT * WD)            // 16384
#define KW      7
#define PADR    3
#define TILEH   32
#define TILEW   16
#define TRH     (TILEH + 2 * PADR)   // 38
#define TRW     (TILEW + 2 * PADR)   // 22
#define NPIX    (TRH * TRW)          // 836
#define NTHREADS 1024                // 32 warps; warp w owns center row w
#define NCENT   512                  // centers per block
#define NOFF    (KW * KW)            // 49
#define EPAD    52                   // fp32/center: 208B = 13 granules (odd) -> CF
#define LOG2E   1.4426950408889634f

// smem: fp16 tile [NPIX][64] SW-swizzled | fp32 rnorms [NPIX] | fp32 exps [512][EPAD]
#define TILE_HALVES  (NPIX * 64)
#define TILE_BYTES_S (TILE_HALVES * 2)               // 107,008
#define NORM_BYTES   (NPIX * 4)                      // 3,344
#define EXPS_BYTES   (NCENT * EPAD * 4)              // 106,496
#define SMEM_BYTES   (TILE_BYTES_S + NORM_BYTES + EXPS_BYTES)  // 216,848 B (< 227KB)

__device__ __forceinline__ void ldsm_x4(unsigned& r0, unsigned& r1,
                                        unsigned& r2, unsigned& r3, unsigned addr) {
    asm volatile("ldmatrix.sync.aligned.m8n8.x4.shared.b16 {%0,%1,%2,%3},[%4];"
                 : "=r"(r0), "=r"(r1), "=r"(r2), "=r"(r3) : "r"(addr));
}
__device__ __forceinline__ void mma16816(float& d0, float& d1, float& d2, float& d3,
                                         unsigned a0, unsigned a1, unsigned a2, unsigned a3,
                                         unsigned b0, unsigned b1) {
    asm volatile("mma.sync.aligned.m16n8k16.row.col.f32.f16.f16.f32 "
                 "{%0,%1,%2,%3},{%4,%5,%6,%7},{%8,%9},{%0,%1,%2,%3};"
                 : "+f"(d0), "+f"(d1), "+f"(d2), "+f"(d3)
                 : "r"(a0), "r"(a1), "r"(a2), "r"(a3), "r"(b0), "r"(b1));
}
__device__ __forceinline__ float ex2f(float x) {
    float y; asm("ex2.approx.f32 %0, %1;" : "=f"(y) : "f"(x)); return y;
}

__global__ __launch_bounds__(NTHREADS, 1)
void region_sim_kernel(const float* __restrict__ x, float* __restrict__ out) {
    extern __shared__ __align__(16) char smem_raw[];
    __half* tile   = (__half*)smem_raw;                              // [NPIX][64]
    float*  rnorms = (float*)(smem_raw + TILE_BYTES_S);              // [NPIX]
    float*  exps   = (float*)(smem_raw + TILE_BYTES_S + NORM_BYTES); // [512][EPAD]

    const int b   = blockIdx.z;
    const int w0  = blockIdx.x * TILEW;
    const int h0  = blockIdx.y * TILEH;
    const int tid = threadIdx.x;

    // ---- Phase 1 (fused): gmem fp32 -> fp16 tile + rnorm, single pass (1024 thr) ----
    const float* xb = x + (size_t)b * CHN * HW;
#pragma unroll 1
    for (int p = tid; p < NPIX; p += NTHREADS) {
        int r   = p / TRW;
        int col = p - r * TRW;
        int gh  = h0 - PADR + r;
        int gw  = w0 - PADR + col;
        const bool inb = (gh >= 0 && gh < HT && gw >= 0 && gw < WD);
        const int gi = gh * WD + gw;
        __half2* tp = (__half2*)(tile + p * 64);
        const int sw = p & 7;
        float4 s = make_float4(0.f, 0.f, 0.f, 0.f);
#pragma unroll
        for (int q = 0; q < 8; q++) {
            __half2 h0v = __float2half2_rn(0.f), h1v = h0v, h2v = h0v, h3v = h0v;
            if (inb) {
                const float* x0 = xb + (size_t)(q * 8) * HW + gi;
                h0v = __floats2half2_rn(x0[0],      x0[HW]);
                h1v = __floats2half2_rn(x0[2 * HW], x0[3 * HW]);
                h2v = __floats2half2_rn(x0[4 * HW], x0[5 * HW]);
                h3v = __floats2half2_rn(x0[6 * HW], x0[7 * HW]);
            }
            __half2* dst = tp + (size_t)(q ^ sw) * 4;
            dst[0] = h0v; dst[1] = h1v; dst[2] = h2v; dst[3] = h3v;
            float2 f0 = __half22float2(h0v);
            float2 f1 = __half22float2(h1v);
            float2 f2 = __half22float2(h2v);
            float2 f3 = __half22float2(h3v);
            s.x += f0.x * f0.x + f2.x * f2.x;
            s.y += f0.y * f0.y + f2.y * f2.y;
            s.z += f1.x * f1.x + f3.x * f3.x;
            s.w += f1.y * f1.y + f3.y * f3.y;
        }
        float ss = (s.x + s.y) + (s.z + s.w);
        rnorms[p] = rsqrtf(ss + 1e-12f);   // padded zeros: dot==0 -> sim=0 -> e=1 (ref match)
    }
    __syncthreads();

    // ---- Phase 3: Gram-band via mma.sync; warp w -> center row w (0..31) ----
    const int w    = tid >> 5;
    const int lane = tid & 31;
    const unsigned tile_b = (unsigned)__cvta_generic_to_shared(tile);

    const int a_row = (lane & 7) + (((lane >> 3) & 1) << 3);  // 0..15
    const int a_sel = lane >> 4;
    const int b_pix = lane & 7;
    const int b_grp = lane >> 3;

    const int rCt  = PADR + w;
    const int pa0  = rCt * TRW + PADR;
    const int cbase = w * 16;

    // A fragments: 16 centers x 64ch, 4 k-steps (1 ldsm_x4 each)
    unsigned Af[4][4];
    {
        const int pixA = pa0 + a_row;
        const unsigned baseA = tile_b + pixA * 128;
        const int swA = pixA & 7;
#pragma unroll
        for (int ks = 0; ks < 4; ks++)
            ldsm_x4(Af[ks][0], Af[ks][1], Af[ks][2], Af[ks][3],
                    baseA + (((2 * ks + a_sel) ^ swA) << 4));
    }

    const int m0 = lane >> 2;
    const float rnA0 = rnorms[pa0 + m0]     * LOG2E;
    const float rnA1 = rnorms[pa0 + m0 + 8] * LOG2E;
    float* eb0 = exps + (cbase + m0) * EPAD;
    float* eb1 = eb0 + 8 * EPAD;
    const int n_of = (lane & 3) << 1;

#pragma unroll 1
    for (int o = 0; o < 7; o++) {
        const int pb = (rCt - 3 + o) * TRW;
        const float* rnb = rnorms + pb;
        const int ko = o * 7;
#pragma unroll
        for (int nt = 0; nt < 3; nt++) {
            const int pixB = pb + nt * 8 + b_pix;
            const unsigned baseB = tile_b + pixB * 128;
            const int swB = pixB & 7;
            unsigned b0, b1, b2, b3, b4, b5, b6, b7;
            ldsm_x4(b0, b1, b2, b3, baseB + (((b_grp)     ^ swB) << 4));
            ldsm_x4(b4, b5, b6, b7, baseB + (((b_grp + 4) ^ swB) << 4));
            float d0 = 0.f, d1 = 0.f, d2 = 0.f, d3 = 0.f;
            mma16816(d0, d1, d2, d3, Af[0][0], Af[0][1], Af[0][2], Af[0][3], b0, b1);
            mma16816(d0, d1, d2, d3, Af[1][0], Af[1][1], Af[1][2], Af[1][3], b2, b3);
            mma16816(d0, d1, d2, d3, Af[2][0], Af[2][1], Af[2][2], Af[2][3], b4, b5);
            mma16816(d0, d1, d2, d3, Af[3][0], Af[3][1], Af[3][2], Af[3][3], b6, b7);
            const float dd[4] = {d0, d1, d2, d3};
#pragma unroll
            for (int e4 = 0; e4 < 4; e4++) {
                const int m = (e4 & 2) ? m0 + 8 : m0;
                const int n = nt * 8 + n_of + (e4 & 1);
                const int kc = n - m;
                if ((unsigned)kc <= 6u) {
                    const float rnA = (e4 & 2) ? rnA1 : rnA0;
                    float sim2 = dd[e4] * (rnA * rnb[n]);   // sim * log2e
                    ((e4 & 2) ? eb1 : eb0)[ko + kc] = ex2f(sim2);   // fp32: no F2H
                }
            }
        }
    }
    __syncthreads();

    // ---- Phase 4: softmax normalize + stores, split across ALL 1024 threads ----
    {
        const int c  = tid & (NCENT - 1);     // center 0..511
        const int hi = tid >> 9;              // 0: kk 0..23, 1: kk 24..48
        const float* my_exps = exps + c * EPAD;
        float den = 0.f;
#pragma unroll
        for (int g = 0; g < 12; g++) {        // 12 x float4 = 48 (conflict-free)
            float4 v = *(const float4*)(my_exps + g * 4);
            den += (v.x + v.y) + (v.z + v.w);
        }
        den += my_exps[48];
        const float ri = __fdividef(1.f, den);

        const int lw = c & (TILEW - 1);
        const int lh = c >> 4;
        const size_t obase = (size_t)b * NOFF * HW + (size_t)(h0 + lh) * WD + (w0 + lw);
        const int g0 = hi * 6;
#pragma unroll 1
        for (int g = g0; g < g0 + 6; g++) {   // 6 float4-groups per half
            float4 v = *(const float4*)(my_exps + g * 4);
            const size_t ob = obase + (size_t)(g * 4) * HW;
            out[ob]          = v.x * ri;
            out[ob + HW]     = v.y * ri;
            out[ob + 2 * HW] = v.z * ri;
            out[ob + 3 * HW] = v.w * ri;
        }
        if (hi)
            out[obase + (size_t)48 * HW] = my_exps[48] * ri;
    }
}

extern "C" void kernel_launch(void* const* d_in, const int* in_sizes, int n_in,
                              void* d_out, int out_size) {
    (void)in_sizes; (void)n_in; (void)out_size;
    const float* x = (const float*)d_in[0];
    float* out = (float*)d_out;

    cudaFuncSetAttribute(region_sim_kernel,
                         cudaFuncAttributeMaxDynamicSharedMemorySize, SMEM_BYTES);

    dim3 grid(WD / TILEW, HT / TILEH, BATCH);   // 8 x 4 x 4 = 128 blocks = 1 wave
    region_sim_kernel<<<grid, NTHREADS, SMEM_BYTES>>>(x, out);
}

// round 15
// speedup vs baseline: 1.0755x; 1.0755x over previous
#include <cuda_runtime.h>
#include <cuda_fp16.h>
#include <math.h>

// x = (4, 64, 128, 128) fp32, K=7 -> out (4, 49, 16384) fp32
#define BATCH   4
#define CHN     64
#define HT      128
#define WD      128
#define HW      (HT * WD)            // 16384
#define KW      7
#define PADR    3
#define TILEH   32
#define TILEW   16
#define TRH     (TILEH + 2 * PADR)   // 38
#define TRW     (TILEW + 2 * PADR)   // 22
#define NPIX    (TRH * TRW)          // 836
#define NTHREADS 1024                // 32 warps; warp w owns center row w
#define NCENT   512                  // centers per block
#define NOFF    (KW * KW)            // 49
#define EPAD    56                   // 112B/center: 7 granules (odd) -> conflict-free
#define LOG2E   1.4426950408889634f

// smem: fp16 tile [NPIX][64] SW-swizzled | fp32 rnorms [NPIX] | fp16 exps [512][EPAD]
#define TILE_HALVES  (NPIX * 64)
#define TILE_BYTES_S (TILE_HALVES * 2)               // 107,008
#define NORM_BYTES   (NPIX * 4)                      // 3,344
#define EXPS_BYTES   (NCENT * EPAD * 2)              // 57,344
#define SMEM_BYTES   (TILE_BYTES_S + NORM_BYTES + EXPS_BYTES)  // 167,696 B

__device__ __forceinline__ void ldsm_x4(unsigned& r0, unsigned& r1,
                                        unsigned& r2, unsigned& r3, unsigned addr) {
    asm volatile("ldmatrix.sync.aligned.m8n8.x4.shared.b16 {%0,%1,%2,%3},[%4];"
                 : "=r"(r0), "=r"(r1), "=r"(r2), "=r"(r3) : "r"(addr));
}
__device__ __forceinline__ void mma16816(float& d0, float& d1, float& d2, float& d3,
                                         unsigned a0, unsigned a1, unsigned a2, unsigned a3,
                                         unsigned b0, unsigned b1) {
    asm volatile("mma.sync.aligned.m16n8k16.row.col.f32.f16.f16.f32 "
                 "{%0,%1,%2,%3},{%4,%5,%6,%7},{%8,%9},{%0,%1,%2,%3};"
                 : "+f"(d0), "+f"(d1), "+f"(d2), "+f"(d3)
                 : "r"(a0), "r"(a1), "r"(a2), "r"(a3), "r"(b0), "r"(b1));
}
__device__ __forceinline__ float ex2f(float x) {
    float y; asm("ex2.approx.f32 %0, %1;" : "=f"(y) : "f"(x)); return y;
}

__global__ __launch_bounds__(NTHREADS, 1)
void region_sim_kernel(const float* __restrict__ x, float* __restrict__ out) {
    extern __shared__ __align__(16) char smem_raw[];
    __half* tile   = (__half*)smem_raw;                               // [NPIX][64]
    float*  rnorms = (float*)(smem_raw + TILE_BYTES_S);               // [NPIX]
    __half* exps   = (__half*)(smem_raw + TILE_BYTES_S + NORM_BYTES); // [512][EPAD]

    const int b   = blockIdx.z;
    const int w0  = blockIdx.x * TILEW;
    const int h0  = blockIdx.y * TILEH;
    const int tid = threadIdx.x;

    // ---- Phase 1 (fused): gmem fp32 -> fp16 tile + rnorm, single pass (1024 thr) ----
    const float* xb = x + (size_t)b * CHN * HW;
#pragma unroll 1
    for (int p = tid; p < NPIX; p += NTHREADS) {
        int r   = p / TRW;
        int col = p - r * TRW;
        int gh  = h0 - PADR + r;
        int gw  = w0 - PADR + col;
        const bool inb = (gh >= 0 && gh < HT && gw >= 0 && gw < WD);
        const int gi = gh * WD + gw;
        __half2* tp = (__half2*)(tile + p * 64);
        const int sw = p & 7;
        float4 s = make_float4(0.f, 0.f, 0.f, 0.f);
#pragma unroll
        for (int q = 0; q < 8; q++) {
            __half2 h0v = __float2half2_rn(0.f), h1v = h0v, h2v = h0v, h3v = h0v;
            if (inb) {
                const float* x0 = xb + (size_t)(q * 8) * HW + gi;
                h0v = __floats2half2_rn(x0[0],      x0[HW]);
                h1v = __floats2half2_rn(x0[2 * HW], x0[3 * HW]);
                h2v = __floats2half2_rn(x0[4 * HW], x0[5 * HW]);
                h3v = __floats2half2_rn(x0[6 * HW], x0[7 * HW]);
            }
            __half2* dst = tp + (size_t)(q ^ sw) * 4;
            dst[0] = h0v; dst[1] = h1v; dst[2] = h2v; dst[3] = h3v;
            float2 f0 = __half22float2(h0v);
            float2 f1 = __half22float2(h1v);
            float2 f2 = __half22float2(h2v);
            float2 f3 = __half22float2(h3v);
            s.x += f0.x * f0.x + f2.x * f2.x;
            s.y += f0.y * f0.y + f2.y * f2.y;
            s.z += f1.x * f1.x + f3.x * f3.x;
            s.w += f1.y * f1.y + f3.y * f3.y;
        }
        float ss = (s.x + s.y) + (s.z + s.w);
        rnorms[p] = rsqrtf(ss + 1e-12f);   // padded zeros: dot==0 -> sim=0 -> e=1 (ref match)
    }
    __syncthreads();

    // ---- Phase 3: Gram-band via mma.sync; warp w -> center row w (0..31) ----
    const int w    = tid >> 5;
    const int lane = tid & 31;
    const unsigned tile_b = (unsigned)__cvta_generic_to_shared(tile);

    const int a_row = (lane & 7) + (((lane >> 3) & 1) << 3);  // 0..15
    const int a_sel = lane >> 4;
    const int b_pix = lane & 7;
    const int b_grp = lane >> 3;

    const int rCt  = PADR + w;
    const int pa0  = rCt * TRW + PADR;
    const int cbase = w * 16;

    // A fragments: 16 centers x 64ch, 4 k-steps (1 ldsm_x4 each)
    unsigned Af[4][4];
    {
        const int pixA = pa0 + a_row;
        const unsigned baseA = tile_b + pixA * 128;
        const int swA = pixA & 7;
#pragma unroll
        for (int ks = 0; ks < 4; ks++)
            ldsm_x4(Af[ks][0], Af[ks][1], Af[ks][2], Af[ks][3],
                    baseA + (((2 * ks + a_sel) ^ swA) << 4));
    }

    const int m0 = lane >> 2;
    const float rnA0 = rnorms[pa0 + m0]     * LOG2E;
    const float rnA1 = rnorms[pa0 + m0 + 8] * LOG2E;
    __half* eb0 = exps + (cbase + m0) * EPAD;
    __half* eb1 = eb0 + 8 * EPAD;
    const int n_of = (lane & 3) << 1;

#pragma unroll 1
    for (int o = 0; o < 7; o++) {
        const int pb = (rCt - 3 + o) * TRW;
        const float* rnb = rnorms + pb;
        const int ko = o * 7;
#pragma unroll
        for (int nt = 0; nt < 3; nt++) {
            const int pixB = pb + nt * 8 + b_pix;
            const unsigned baseB = tile_b + pixB * 128;
            const int swB = pixB & 7;
            unsigned b0, b1, b2, b3, b4, b5, b6, b7;
            ldsm_x4(b0, b1, b2, b3, baseB + (((b_grp)     ^ swB) << 4));
            ldsm_x4(b4, b5, b6, b7, baseB + (((b_grp + 4) ^ swB) << 4));
            float d0 = 0.f, d1 = 0.f, d2 = 0.f, d3 = 0.f;
            mma16816(d0, d1, d2, d3, Af[0][0], Af[0][1], Af[0][2], Af[0][3], b0, b1);
            mma16816(d0, d1, d2, d3, Af[1][0], Af[1][1], Af[1][2], Af[1][3], b2, b3);
            mma16816(d0, d1, d2, d3, Af[2][0], Af[2][1], Af[2][2], Af[2][3], b4, b5);
            mma16816(d0, d1, d2, d3, Af[3][0], Af[3][1], Af[3][2], Af[3][3], b6, b7);
            const float dd[4] = {d0, d1, d2, d3};
#pragma unroll
            for (int e4 = 0; e4 < 4; e4++) {
                const int m = (e4 & 2) ? m0 + 8 : m0;
                const int n = nt * 8 + n_of + (e4 & 1);
                const int kc = n - m;
                if ((unsigned)kc <= 6u) {
                    const float rnA = (e4 & 2) ? rnA1 : rnA0;
                    float sim2 = dd[e4] * (rnA * rnb[n]);   // sim * log2e
                    __half eh = __float2half_rn(ex2f(sim2));
                    ((e4 & 2) ? eb1 : eb0)[ko + kc] = eh;
                }
            }
        }
    }
    __syncthreads();

    // ---- Phase 4: softmax normalize + stores, split across ALL 1024 threads ----
    {
        const int c  = tid & (NCENT - 1);     // center 0..511
        const int hi = tid >> 9;              // 0: kk 0..23, 1: kk 24..48
        const __half* my_exps = exps + c * EPAD;
        float den = 0.f;
#pragma unroll
        for (int g = 0; g < 6; g++) {
            uint4 hv = *(const uint4*)(my_exps + g * 8);
            float2 f0 = __half22float2(*(__half2*)&hv.x);
            float2 f1 = __half22float2(*(__half2*)&hv.y);
            float2 f2 = __half22float2(*(__half2*)&hv.z);
            float2 f3 = __half22float2(*(__half2*)&hv.w);
            den += ((f0.x + f0.y) + (f1.x + f1.y)) + ((f2.x + f2.y) + (f3.x + f3.y));
        }
        den += __half2float(my_exps[48]);
        const float ri = __fdividef(1.f, den);

        const int lw = c & (TILEW - 1);
        const int lh = c >> 4;
        const size_t obase = (size_t)b * NOFF * HW + (size_t)(h0 + lh) * WD + (w0 + lw);
        const int g0 = hi * 3;
#pragma unroll 1
        for (int g = g0; g < g0 + 3; g++) {   // 3 groups of 8 per half-thread
            uint4 hv = *(const uint4*)(my_exps + g * 8);
            float2 f0 = __half22float2(*(__half2*)&hv.x);
            float2 f1 = __half22float2(*(__half2*)&hv.y);
            float2 f2 = __half22float2(*(__half2*)&hv.z);
            float2 f3 = __half22float2(*(__half2*)&hv.w);
            const size_t ob = obase + (size_t)(g * 8) * HW;
            out[ob]          = f0.x * ri;
            out[ob + HW]     = f0.y * ri;
            out[ob + 2 * HW] = f1.x * ri;
            out[ob + 3 * HW] = f1.y * ri;
            out[ob + 4 * HW] = f2.x * ri;
            out[ob + 5 * HW] = f2.y * ri;
            out[ob + 6 * HW] = f3.x * ri;
            out[ob + 7 * HW] = f3.y * ri;
        }
        if (hi)
            out[obase + (size_t)48 * HW] = __half2float(my_exps[48]) * ri;
    }
}

extern "C" void kernel_launch(void* const* d_in, const int* in_sizes, int n_in,
                              void* d_out, int out_size) {
    (void)in_sizes; (void)n_in; (void)out_size;
    const float* x = (const float*)d_in[0];
    float* out = (float*)d_out;

    cudaFuncSetAttribute(region_sim_kernel,
                         cudaFuncAttributeMaxDynamicSharedMemorySize, SMEM_BYTES);

    dim3 grid(WD / TILEW, HT / TILEH, BATCH);   // 8 x 4 x 4 = 128 blocks = 1 wave
    region_sim_kernel<<<grid, NTHREADS, SMEM_BYTES>>>(x, out);
}

// round 16
// speedup vs baseline: 1.1083x; 1.0305x over previous
#include <cuda_runtime.h>
#include <cuda_fp16.h>
#include <math.h>

// x = (4, 64, 128, 128) fp32, K=7 -> out (4, 49, 16384) fp32
#define BATCH   4
#define CHN     64
#define HT      128
#define WD      128
#define HW      (HT * WD)            // 16384
#define KW      7
#define PADR    3
#define TILEH   32
#define TILEW   16
#define TRH     (TILEH + 2 * PADR)   // 38
#define TRW     (TILEW + 2 * PADR)   // 22
#define NPIX    (TRH * TRW)          // 836
#define NTHREADS 1024                // 32 warps; warp w owns center row w
#define NCENT   512                  // centers per block
#define NOFF    (KW * KW)            // 49
#define EPAD    56                   // 112B/center: 7 granules (odd) -> conflict-free
#define LOG2E   1.4426950408889634f

// smem: fp16 tile [NPIX][64] SW-swizzled | fp32 rnorms [NPIX] | fp16 exps [512][EPAD]
#define TILE_HALVES  (NPIX * 64)
#define TILE_BYTES_S (TILE_HALVES * 2)               // 107,008
#define NORM_BYTES   (NPIX * 4)                      // 3,344
#define EXPS_BYTES   (NCENT * EPAD * 2)              // 57,344
#define SMEM_BYTES   (TILE_BYTES_S + NORM_BYTES + EXPS_BYTES)  // 167,696 B

__device__ __forceinline__ void ldsm_x4(unsigned& r0, unsigned& r1,
                                        unsigned& r2, unsigned& r3, unsigned addr) {
    asm volatile("ldmatrix.sync.aligned.m8n8.x4.shared.b16 {%0,%1,%2,%3},[%4];"
                 : "=r"(r0), "=r"(r1), "=r"(r2), "=r"(r3) : "r"(addr));
}
__device__ __forceinline__ void mma16816(float& d0, float& d1, float& d2, float& d3,
                                         unsigned a0, unsigned a1, unsigned a2, unsigned a3,
                                         unsigned b0, unsigned b1) {
    asm volatile("mma.sync.aligned.m16n8k16.row.col.f32.f16.f16.f32 "
                 "{%0,%1,%2,%3},{%4,%5,%6,%7},{%8,%9},{%0,%1,%2,%3};"
                 : "+f"(d0), "+f"(d1), "+f"(d2), "+f"(d3)
                 : "r"(a0), "r"(a1), "r"(a2), "r"(a3), "r"(b0), "r"(b1));
}
__device__ __forceinline__ float ex2f(float x) {
    float y; asm("ex2.approx.f32 %0, %1;" : "=f"(y) : "f"(x)); return y;
}

__global__ __launch_bounds__(NTHREADS, 1)
void region_sim_kernel(const float* __restrict__ x, float* __restrict__ out) {
    extern __shared__ __align__(16) char smem_raw[];
    __half* tile   = (__half*)smem_raw;                               // [NPIX][64]
    float*  rnorms = (float*)(smem_raw + TILE_BYTES_S);               // [NPIX]
    __half* exps   = (__half*)(smem_raw + TILE_BYTES_S + NORM_BYTES); // [512][EPAD]

    const int b   = blockIdx.z;
    const int w0  = blockIdx.x * TILEW;
    const int h0  = blockIdx.y * TILEH;
    const int tid = threadIdx.x;

    // ---- Phase 1 (fused): gmem fp32 -> fp16 tile + rnorm, single pass (1024 thr) ----
    const float* xb = x + (size_t)b * CHN * HW;
#pragma unroll 1
    for (int p = tid; p < NPIX; p += NTHREADS) {
        int r   = p / TRW;
        int col = p - r * TRW;
        int gh  = h0 - PADR + r;
        int gw  = w0 - PADR + col;
        const bool inb = (gh >= 0 && gh < HT && gw >= 0 && gw < WD);
        const int gi = gh * WD + gw;
        __half2* tp = (__half2*)(tile + p * 64);
        const int sw = p & 7;
        float4 s = make_float4(0.f, 0.f, 0.f, 0.f);
#pragma unroll
        for (int q = 0; q < 8; q++) {
            __half2 h0v = __float2half2_rn(0.f), h1v = h0v, h2v = h0v, h3v = h0v;
            if (inb) {
                const float* x0 = xb + (size_t)(q * 8) * HW + gi;
                h0v = __floats2half2_rn(x0[0],      x0[HW]);
                h1v = __floats2half2_rn(x0[2 * HW], x0[3 * HW]);
                h2v = __floats2half2_rn(x0[4 * HW], x0[5 * HW]);
                h3v = __floats2half2_rn(x0[6 * HW], x0[7 * HW]);
            }
            __half2* dst = tp + (size_t)(q ^ sw) * 4;
            dst[0] = h0v; dst[1] = h1v; dst[2] = h2v; dst[3] = h3v;
            float2 f0 = __half22float2(h0v);
            float2 f1 = __half22float2(h1v);
            float2 f2 = __half22float2(h2v);
            float2 f3 = __half22float2(h3v);
            s.x += f0.x * f0.x + f2.x * f2.x;
            s.y += f0.y * f0.y + f2.y * f2.y;
            s.z += f1.x * f1.x + f3.x * f3.x;
            s.w += f1.y * f1.y + f3.y * f3.y;
        }
        float ss = (s.x + s.y) + (s.z + s.w);
        rnorms[p] = rsqrtf(ss + 1e-12f);   // padded zeros: dot==0 -> sim=0 -> e=1 (ref match)
    }
    __syncthreads();

    // ---- Phase 3: Gram-band via mma.sync; warp w -> center row w (0..31) ----
    const int w    = tid >> 5;
    const int lane = tid & 31;
    const unsigned tile_b = (unsigned)__cvta_generic_to_shared(tile);

    const int a_row = (lane & 7) + (((lane >> 3) & 1) << 3);  // 0..15
    const int a_sel = lane >> 4;
    const int b_pix = lane & 7;
    const int b_grp = lane >> 3;

    const int rCt  = PADR + w;
    const int pa0  = rCt * TRW + PADR;
    const int cbase = w * 16;

    // A fragments: 16 centers x 64ch, 4 k-steps (1 ldsm_x4 each)
    unsigned Af[4][4];
    {
        const int pixA = pa0 + a_row;
        const unsigned baseA = tile_b + pixA * 128;
        const int swA = pixA & 7;
#pragma unroll
        for (int ks = 0; ks < 4; ks++)
            ldsm_x4(Af[ks][0], Af[ks][1], Af[ks][2], Af[ks][3],
                    baseA + (((2 * ks + a_sel) ^ swA) << 4));
    }

    const int m0 = lane >> 2;
    const float rnA0 = rnorms[pa0 + m0]     * LOG2E;
    const float rnA1 = rnorms[pa0 + m0 + 8] * LOG2E;
    __half* eb0 = exps + (cbase + m0) * EPAD;
    __half* eb1 = eb0 + 8 * EPAD;
    const int n_of = (lane & 3) << 1;

#pragma unroll 1
    for (int o = 0; o < 7; o++) {
        const int pb = (rCt - 3 + o) * TRW;
        const float* rnb = rnorms + pb;
        const int ko = o * 7;
#pragma unroll
        for (int nt = 0; nt < 3; nt++) {    // nt is compile-time (unrolled)
            const int pixB = pb + nt * 8 + b_pix;
            const unsigned baseB = tile_b + pixB * 128;
            const int swB = pixB & 7;
            unsigned b0, b1, b2, b3, b4, b5, b6, b7;
            ldsm_x4(b0, b1, b2, b3, baseB + (((b_grp)     ^ swB) << 4));
            ldsm_x4(b4, b5, b6, b7, baseB + (((b_grp + 4) ^ swB) << 4));
            float d0 = 0.f, d1 = 0.f, d2 = 0.f, d3 = 0.f;
            mma16816(d0, d1, d2, d3, Af[0][0], Af[0][1], Af[0][2], Af[0][3], b0, b1);
            mma16816(d0, d1, d2, d3, Af[1][0], Af[1][1], Af[1][2], Af[1][3], b2, b3);
            mma16816(d0, d1, d2, d3, Af[2][0], Af[2][1], Af[2][2], Af[2][3], b4, b5);
            mma16816(d0, d1, d2, d3, Af[3][0], Af[3][1], Af[3][2], Af[3][3], b6, b7);

            // Specialized band extraction — statically-dead slots removed:
            //   nt=0: m=m0+8 rows give kc<0 for ALL lanes  -> only e4 0,1
            //   nt=2: m=m0   rows give kc>=9 for ALL lanes -> only e4 2,3
            const int nb0 = nt * 8 + n_of;
            if (nt != 2) {                       // e4 = 0,1 (m = m0, eb0, rnA0)
                const float dd01[2] = {d0, d1};
#pragma unroll
                for (int e = 0; e < 2; e++) {
                    const int n  = nb0 + e;
                    const int kc = n - m0;
                    if ((unsigned)kc <= 6u) {
                        float sim2 = dd01[e] * (rnA0 * rnb[n]);   // sim * log2e
                        eb0[ko + kc] = __float2half_rn(ex2f(sim2));
                    }
                }
            }
            if (nt != 0) {                       // e4 = 2,3 (m = m0+8, eb1, rnA1)
                const float dd23[2] = {d2, d3};
#pragma unroll
                for (int e = 0; e < 2; e++) {
                    const int n  = nb0 + e;
                    const int kc = n - (m0 + 8);
                    if ((unsigned)kc <= 6u) {
                        float sim2 = dd23[e] * (rnA1 * rnb[n]);   // sim * log2e
                        eb1[ko + kc] = __float2half_rn(ex2f(sim2));
                    }
                }
            }
        }
    }
    __syncthreads();

    // ---- Phase 4: per-center softmax normalize + coalesced stores (tid < 512) ----
    if (tid < NCENT) {
        const __half* my_exps = exps + tid * EPAD;
        float den = 0.f;
#pragma unroll
        for (int g = 0; g < 6; g++) {
            uint4 hv = *(const uint4*)(my_exps + g * 8);
            float2 f0 = __half22float2(*(__half2*)&hv.x);
            float2 f1 = __half22float2(*(__half2*)&hv.y);
            float2 f2 = __half22float2(*(__half2*)&hv.z);
            float2 f3 = __half22float2(*(__half2*)&hv.w);
            den += ((f0.x + f0.y) + (f1.x + f1.y)) + ((f2.x + f2.y) + (f3.x + f3.y));
        }
        den += __half2float(my_exps[48]);
        const float ri = __fdividef(1.f, den);

        const int lw = tid & (TILEW - 1);
        const int lh = tid >> 4;
        const size_t obase = (size_t)b * NOFF * HW + (size_t)(h0 + lh) * WD + (w0 + lw);
#pragma unroll 1
        for (int g = 0; g < 6; g++) {
            uint4 hv = *(const uint4*)(my_exps + g * 8);
            float2 f0 = __half22float2(*(__half2*)&hv.x);
            float2 f1 = __half22float2(*(__half2*)&hv.y);
            float2 f2 = __half22float2(*(__half2*)&hv.z);
            float2 f3 = __half22float2(*(__half2*)&hv.w);
            const size_t ob = obase + (size_t)(g * 8) * HW;
            out[ob]          = f0.x * ri;
            out[ob + HW]     = f0.y * ri;
            out[ob + 2 * HW] = f1.x * ri;
            out[ob + 3 * HW] = f1.y * ri;
            out[ob + 4 * HW] = f2.x * ri;
            out[ob + 5 * HW] = f2.y * ri;
            out[ob + 6 * HW] = f3.x * ri;
            out[ob + 7 * HW] = f3.y * ri;
        }
        out[obase + (size_t)48 * HW] = __half2float(my_exps[48]) * ri;
    }
}

extern "C" void kernel_launch(void* const* d_in, const int* in_sizes, int n_in,
                              void* d_out, int out_size) {
    (void)in_sizes; (void)n_in; (void)out_size;
    const float* x = (const float*)d_in[0];
    float* out = (float*)d_out;

    cudaFuncSetAttribute(region_sim_kernel,
                         cudaFuncAttributeMaxDynamicSharedMemorySize, SMEM_BYTES);

    dim3 grid(WD / TILEW, HT / TILEH, BATCH);   // 8 x 4 x 4 = 128 blocks = 1 wave
    region_sim_kernel<<<grid, NTHREADS, SMEM_BYTES>>>(x, out);
}